// round 16
// baseline (speedup 1.0000x reference)
#include <cuda_runtime.h>

// ChamferLoss: B=8, N=M=8192, D=3 fp32, inputs ~ N(0,1).
// out = mean_n min_m ||gt_n - pred_m||^2 + mean_m min_n ||pred_m - gt_n||^2
//
// Grid-accelerated exact NN, G=32, bitmask + lower-bound pruning (R14).
// R15 changes:
//  - strided warp->slot mapping in k_query: each block samples 8 spread
//    spatial regions (same sb), fixing dense-core block imbalance; warp
//    coherence unchanged.
//  - candidates repacked into paired f32x2 SoA (pA={x01,y01}, pB={z01,w01});
//    candidate eval becomes 2 LDG.128 + 3 FFMA2 + 2 FMNMX per 2 candidates.
//    Runs rounded outward to pair boundaries: the <=2 extra points per run
//    are real same-side points, so the min (and exactness) is unaffected.

#define BATCH   8
#define NPTS    8192
#define G       32
#define CELLS   (G * G * G)
#define NROWS   (G * G)
#define NSB     (2 * BATCH)
#define RANGE   6.0f
#define HCELL   (2.0f * RANGE / G)     // 0.375
#define INVH    ((float)G / (2.0f * RANGE))
#define NTOT    (NSB * NPTS)           // 131072
#define SEG     (CELLS / 1024)         // 32
#define FINF    3.402823466e+38f

__device__ int        g_offs [NSB * (CELLS + 1)];
__device__ unsigned   g_bits [NSB * NROWS];
__device__ float4     g_sorted[NSB * NPTS];        // {x,y,z,b2}
__device__ int        g_sidx  [NSB * NPTS];
__device__ ulonglong2 g_pA[NSB * NPTS / 2];        // {x01, y01} packed f32x2
__device__ ulonglong2 g_pB[NSB * NPTS / 2];        // {z01, w01}
__device__ float      g_minbuf[NSB * NPTS];
__device__ float      g_blocksums[512];

__device__ __forceinline__ void cell_of(float x, float y, float z,
                                        int& cx, int& cy, int& cz) {
    cx = min(G - 1, max(0, (int)floorf((x + RANGE) * INVH)));
    cy = min(G - 1, max(0, (int)floorf((y + RANGE) * INVH)));
    cz = min(G - 1, max(0, (int)floorf((z + RANGE) * INVH)));
}

__device__ __forceinline__ unsigned range_mask(int lo, int hi) {
    unsigned m = (hi >= 31) ? 0xFFFFFFFFu : ((1u << (hi + 1)) - 1u);
    return m & ~((1u << lo) - 1u);
}

__device__ __forceinline__ unsigned long long pack2(float lo, float hi) {
    unsigned long long r;
    asm("mov.b64 %0, {%1, %2};" : "=l"(r) : "f"(lo), "f"(hi));
    return r;
}
__device__ __forceinline__ void unpack2(unsigned long long v, float& lo, float& hi) {
    asm("mov.b64 {%0, %1}, %2;" : "=f"(lo), "=f"(hi) : "l"(v));
}
__device__ __forceinline__ unsigned long long fma2(unsigned long long a,
                                                   unsigned long long b,
                                                   unsigned long long c) {
    unsigned long long d;
    asm("fma.rn.f32x2 %0, %1, %2, %3;" : "=l"(d) : "l"(a), "l"(b), "l"(c));
    return d;
}

// 1. zero offs + bitmask
__global__ __launch_bounds__(256)
void k_zero() {
    int i = blockIdx.x * 256 + threadIdx.x;
    const int NOFF = NSB * (CELLS + 1);
    for (int k = i; k < NOFF; k += gridDim.x * 256) g_offs[k] = 0;
    for (int k = i; k < NSB * NROWS; k += gridDim.x * 256) g_bits[k] = 0u;
}

// 2. count into offs[c+1] + mark nonempty rows
__global__ __launch_bounds__(256)
void k_count(const float* __restrict__ gts, const float* __restrict__ preds) {
    int idx = blockIdx.x * 256 + threadIdx.x;
    int sb  = idx >> 13;
    int i   = idx & (NPTS - 1);
    int side = sb >> 3, b = sb & 7;
    const float* p = (side == 0 ? gts : preds) + ((size_t)b * NPTS + i) * 3;
    int cx, cy, cz;
    cell_of(p[0], p[1], p[2], cx, cy, cz);
    int c = (cz * G + cy) * G + cx;
    atomicAdd(&g_offs[sb * (CELLS + 1) + c + 1], 1);
    atomicOr(&g_bits[sb * NROWS + (cz * G + cy)], 1u << cx);
}

// 3. in-place exclusive scan of positions 1..CELLS per sb
__global__ __launch_bounds__(1024)
void k_scan() {
    const int sb = blockIdx.x;
    const int t  = threadIdx.x;
    int* Q = g_offs + sb * (CELLS + 1);
    const int base = 1 + t * SEG;

    int s = 0;
#pragma unroll
    for (int k = 0; k < SEG; ++k) s += Q[base + k];

    __shared__ int ws[32];
    int lane = t & 31, wid = t >> 5;
    int v = s;
#pragma unroll
    for (int d = 1; d < 32; d <<= 1) {
        int n = __shfl_up_sync(0xFFFFFFFFu, v, d);
        if (lane >= d) v += n;
    }
    if (lane == 31) ws[wid] = v;
    __syncthreads();
    if (wid == 0) {
        int w = ws[lane];
#pragma unroll
        for (int d = 1; d < 32; d <<= 1) {
            int n = __shfl_up_sync(0xFFFFFFFFu, w, d);
            if (lane >= d) w += n;
        }
        ws[lane] = w;
    }
    __syncthreads();
    int run = v - s + (wid ? ws[wid - 1] : 0);

#pragma unroll
    for (int k = 0; k < SEG; ++k) {
        int tmp = Q[base + k];
        Q[base + k] = run;
        run += tmp;
    }
}

// 4. scatter
__global__ __launch_bounds__(256)
void k_scatter(const float* __restrict__ gts, const float* __restrict__ preds) {
    int idx = blockIdx.x * 256 + threadIdx.x;
    int sb  = idx >> 13;
    int i   = idx & (NPTS - 1);
    int side = sb >> 3, b = sb & 7;
    const float* p = (side == 0 ? gts : preds) + ((size_t)b * NPTS + i) * 3;
    float x = p[0], y = p[1], z = p[2];
    int cx, cy, cz;
    cell_of(x, y, z, cx, cy, cz);
    int c   = (cz * G + cy) * G + cx;
    int pos = atomicAdd(&g_offs[sb * (CELLS + 1) + c + 1], 1);
    g_sorted[sb * NPTS + pos] = make_float4(x, y, z, x * x + y * y + z * z);
    g_sidx  [sb * NPTS + pos] = i;
}

// 4b. repack pairs into f32x2 SoA
__global__ __launch_bounds__(256)
void k_repack() {
    int k = blockIdx.x * 256 + threadIdx.x;     // 0..NTOT/2-1
    float4 p0 = g_sorted[2 * k + 0];
    float4 p1 = g_sorted[2 * k + 1];
    ulonglong2 a, b;
    a.x = pack2(p0.x, p1.x);
    a.y = pack2(p0.y, p1.y);
    b.x = pack2(p0.z, p1.z);
    b.y = pack2(p0.w, p1.w);
    g_pA[k] = a;
    g_pB[k] = b;
}

// 5. exact NN query: strided warp mapping + packed pair evaluation
__global__ __launch_bounds__(256)
void k_query() {
    __shared__ unsigned sbits[NROWS];

    const int qsb       = blockIdx.x >> 5;       // 32 blocks per sb
    const int blk_in_sb = blockIdx.x & 31;
    const int warp_in_b = threadIdx.x >> 5;
    const int lane      = threadIdx.x & 31;
    // spread mapping: warp w of block k handles warp-slot w*32+k
    const int slot = (warp_in_b * 32 + blk_in_sb) * 32 + lane;
    const int gsb  = qsb ^ 8;

#pragma unroll
    for (int k = 0; k < NROWS / 256; ++k)
        sbits[threadIdx.x + k * 256] = g_bits[gsb * NROWS + threadIdx.x + k * 256];
    __syncthreads();

    float4 q = g_sorted[qsb * NPTS + slot];      // q.w = |q|^2
    const unsigned long long mqx2 = pack2(-2.0f * q.x, -2.0f * q.x);
    const unsigned long long mqy2 = pack2(-2.0f * q.y, -2.0f * q.y);
    const unsigned long long mqz2 = pack2(-2.0f * q.z, -2.0f * q.z);
    int cx, cy, cz;
    cell_of(q.x, q.y, q.z, cx, cy, cz);

    float fx = (q.x + RANGE) * INVH - (float)cx;
    float fy = (q.y + RANGE) * INVH - (float)cy;
    float fz = (q.z + RANGE) * INVH - (float)cz;
    float dxm = fx * HCELL, dxp = (1.0f - fx) * HCELL;
    float dym = fy * HCELL, dyp = (1.0f - fy) * HCELL;
    float dzm = fz * HCELL, dzp = (1.0f - fz) * HCELL;

    const int*        offs = g_offs + gsb * (CELLS + 1);
    const ulonglong2* pA   = g_pA + (size_t)gsb * (NPTS / 2);
    const ulonglong2* pB   = g_pB + (size_t)gsb * (NPTS / 2);

    float bestA = FINF, bestB = FINF;   // lo/hi lane min chains over t=b2-2q.b

#define SCAN_RUN(S, E)                                                        \
    {                                                                         \
        int s_ = (S), e_ = (E);                                               \
        if (e_ > s_) {                                                        \
            int k0 = s_ >> 1, k1 = (e_ + 1) >> 1;  /* round out to pairs */   \
            for (; k0 + 2 <= k1; k0 += 2) {                                   \
                ulonglong2 a0 = pA[k0], b0 = pB[k0];                          \
                ulonglong2 a1 = pA[k0 + 1], b1 = pB[k0 + 1];                  \
                unsigned long long t0 = fma2(mqx2, a0.x, b0.y);               \
                unsigned long long t1 = fma2(mqx2, a1.x, b1.y);               \
                t0 = fma2(mqy2, a0.y, t0);                                    \
                t1 = fma2(mqy2, a1.y, t1);                                    \
                t0 = fma2(mqz2, b0.x, t0);                                    \
                t1 = fma2(mqz2, b1.x, t1);                                    \
                float l0, h0, l1, h1;                                         \
                unpack2(t0, l0, h0);                                          \
                unpack2(t1, l1, h1);                                          \
                bestA = fminf(bestA, fminf(l0, l1));                          \
                bestB = fminf(bestB, fminf(h0, h1));                          \
            }                                                                 \
            for (; k0 < k1; ++k0) {                                           \
                ulonglong2 a0 = pA[k0], b0 = pB[k0];                          \
                unsigned long long t0 = fma2(mqx2, a0.x, b0.y);               \
                t0 = fma2(mqy2, a0.y, t0);                                    \
                t0 = fma2(mqz2, b0.x, t0);                                    \
                float l0, h0;                                                 \
                unpack2(t0, l0, h0);                                          \
                bestA = fminf(bestA, l0);                                     \
                bestB = fminf(bestB, h0);                                     \
            }                                                                 \
        }                                                                     \
    }

    // ---- Phase 1a: center row
    {
        int row = cz * G + cy;
        unsigned m = sbits[row] & range_mask(max(cx - 1, 0), min(cx + 1, G - 1));
        if (m) {
            int x0 = __ffs(m) - 1;
            int x1 = 31 - __clz(m);
            SCAN_RUN(offs[row * G + x0], offs[row * G + x1 + 1]);
        }
    }

    // ---- Phase 1b: 8 remaining rows with exact lower-bound pruning
    {
        const signed char RY[8] = {-1,  1,  0,  0, -1, -1,  1,  1};
        const signed char RZ[8] = { 0,  0, -1,  1, -1,  1, -1,  1};
#pragma unroll
        for (int k = 0; k < 8; ++k) {
            int dy = RY[k], dz = RZ[k];
            int y = cy + dy, z = cz + dz;
            if ((unsigned)y >= G || (unsigned)z >= G) continue;
            float lby = (dy > 0) ? dyp : ((dy < 0) ? dym : 0.0f);
            float lbz = (dz > 0) ? dzp : ((dz < 0) ? dzm : 0.0f);
            float lb2 = lby * lby + lbz * lbz;
            float bd2 = q.w + fminf(bestA, bestB);
            if (lb2 >= bd2) continue;

            unsigned xm = 1u << cx;
            if (cx - 1 >= 0 && lb2 + dxm * dxm < bd2) xm |= 1u << (cx - 1);
            if (cx + 1 <  G && lb2 + dxp * dxp < bd2) xm |= 1u << (cx + 1);
            unsigned m = sbits[z * G + y] & xm;
            if (!m) continue;
            int x0 = __ffs(m) - 1;
            int x1 = 31 - __clz(m);
            int rowb = (z * G + y) * G;
            SCAN_RUN(offs[rowb + x0], offs[rowb + x1 + 1]);
        }
    }

    // ---- Phase 2: rare tail, ring expansion (exact bound)
    if (q.w + fminf(bestA, bestB) > HCELL * HCELL) {
        for (int r = 2; r <= G; ++r) {
            int zlo = max(cz - r, 0), zhi = min(cz + r, G - 1);
            for (int z = zlo; z <= zhi; ++z) {
                int adz = abs(z - cz);
                int ylo = max(cy - r, 0), yhi = min(cy + r, G - 1);
                for (int y = ylo; y <= yhi; ++y) {
                    int ady = abs(y - cy);
                    int row = z * G + y;
                    unsigned m;
                    if (adz == r || ady == r) {
                        m = sbits[row] &
                            range_mask(max(cx - r, 0), min(cx + r, G - 1));
                    } else {
                        unsigned em = 0;
                        if (cx - r >= 0) em |= 1u << (cx - r);
                        if (cx + r < G)  em |= 1u << (cx + r);
                        m = sbits[row] & em;
                    }
                    while (m) {
                        int x = __ffs(m) - 1;
                        m &= m - 1;
                        int c = row * G + x;
                        SCAN_RUN(offs[c], offs[c + 1]);
                    }
                }
            }
            float rb = (float)r * HCELL;
            if (q.w + fminf(bestA, bestB) <= rb * rb) break;
        }
    }
#undef SCAN_RUN

    float v = fmaxf(q.w + fminf(bestA, bestB), 0.0f);
    g_minbuf[qsb * NPTS + g_sidx[qsb * NPTS + slot]] = v;
}

// 6. deterministic block-tree partial sums
__global__ __launch_bounds__(256)
void k_reduce() {
    __shared__ float red[256];
    int i = blockIdx.x * 256 + threadIdx.x;
    red[threadIdx.x] = g_minbuf[i];
    __syncthreads();
#pragma unroll
    for (int s = 128; s > 0; s >>= 1) {
        if (threadIdx.x < s) red[threadIdx.x] += red[threadIdx.x + s];
        __syncthreads();
    }
    if (threadIdx.x == 0) g_blocksums[blockIdx.x] = red[0];
}

// 7. final
__global__ void k_final(float* __restrict__ out) {
    __shared__ float red[512];
    red[threadIdx.x] = g_blocksums[threadIdx.x];
    __syncthreads();
#pragma unroll
    for (int s = 256; s > 0; s >>= 1) {
        if (threadIdx.x < s) red[threadIdx.x] += red[threadIdx.x + s];
        __syncthreads();
    }
    if (threadIdx.x == 0)
        out[0] = red[0] / (float)(BATCH * NPTS);
}

extern "C" void kernel_launch(void* const* d_in, const int* in_sizes, int n_in,
                              void* d_out, int out_size) {
    const float* gts   = (const float*)d_in[0];
    const float* preds = (const float*)d_in[1];
    (void)in_sizes; (void)n_in; (void)out_size;

    k_zero<<<512, 256>>>();
    k_count<<<NTOT / 256, 256>>>(gts, preds);
    k_scan<<<NSB, 1024>>>();
    k_scatter<<<NTOT / 256, 256>>>(gts, preds);
    k_repack<<<NTOT / 512, 256>>>();
    k_query<<<NTOT / 256, 256>>>();
    k_reduce<<<NTOT / 256, 256>>>();
    k_final<<<1, 512>>>((float*)d_out);
}

// round 17
// speedup vs baseline: 1.0363x; 1.0363x over previous
#include <cuda_runtime.h>

// ChamferLoss: B=8, N=M=8192, D=3 fp32, inputs ~ N(0,1).
// out = mean_n min_m ||gt_n - pred_m||^2 + mean_m min_n ||pred_m - gt_n||^2
//
// Grid-accelerated exact NN, G=32, bitmask + lower-bound pruning.
// R16 = R14 baseline (153.7us; R15's spread+packing both reverted) plus:
// center-row pruning — scan the HOME CELL first, then x-neighbors only if
// their wall distance beats the current best (dx_wall^2 < bd2). The earlier,
// tighter bd2 also prunes more side rows. Pruned cells are provably >= bd
// away -> exact min unchanged. Deterministic fixed-order reduction.

#define BATCH   8
#define NPTS    8192
#define G       32
#define CELLS   (G * G * G)
#define NROWS   (G * G)
#define NSB     (2 * BATCH)
#define RANGE   6.0f
#define HCELL   (2.0f * RANGE / G)     // 0.375
#define INVH    ((float)G / (2.0f * RANGE))
#define NTOT    (NSB * NPTS)           // 131072
#define SEG     (CELLS / 1024)         // 32
#define FINF    3.402823466e+38f

__device__ int      g_offs [NSB * (CELLS + 1)];  // +1-shifted counts -> ends
__device__ unsigned g_bits [NSB * NROWS];
__device__ float4   g_sorted[NSB * NPTS];        // {x,y,z,b2}
__device__ int      g_sidx  [NSB * NPTS];
__device__ float    g_minbuf[NSB * NPTS];
__device__ float    g_blocksums[512];

__device__ __forceinline__ void cell_of(float x, float y, float z,
                                        int& cx, int& cy, int& cz) {
    cx = min(G - 1, max(0, (int)floorf((x + RANGE) * INVH)));
    cy = min(G - 1, max(0, (int)floorf((y + RANGE) * INVH)));
    cz = min(G - 1, max(0, (int)floorf((z + RANGE) * INVH)));
}

__device__ __forceinline__ unsigned range_mask(int lo, int hi) {
    unsigned m = (hi >= 31) ? 0xFFFFFFFFu : ((1u << (hi + 1)) - 1u);
    return m & ~((1u << lo) - 1u);
}

// 1. zero offs + bitmask
__global__ __launch_bounds__(256)
void k_zero() {
    int i = blockIdx.x * 256 + threadIdx.x;
    const int NOFF = NSB * (CELLS + 1);
    for (int k = i; k < NOFF; k += gridDim.x * 256) g_offs[k] = 0;
    for (int k = i; k < NSB * NROWS; k += gridDim.x * 256) g_bits[k] = 0u;
}

// 2. count into offs[c+1] + mark nonempty rows
__global__ __launch_bounds__(256)
void k_count(const float* __restrict__ gts, const float* __restrict__ preds) {
    int idx = blockIdx.x * 256 + threadIdx.x;
    int sb  = idx >> 13;
    int i   = idx & (NPTS - 1);
    int side = sb >> 3, b = sb & 7;
    const float* p = (side == 0 ? gts : preds) + ((size_t)b * NPTS + i) * 3;
    int cx, cy, cz;
    cell_of(p[0], p[1], p[2], cx, cy, cz);
    int c = (cz * G + cy) * G + cx;
    atomicAdd(&g_offs[sb * (CELLS + 1) + c + 1], 1);
    atomicOr(&g_bits[sb * NROWS + (cz * G + cy)], 1u << cx);
}

// 3. in-place exclusive scan of positions 1..CELLS per sb (16 x 1024)
__global__ __launch_bounds__(1024)
void k_scan() {
    const int sb = blockIdx.x;
    const int t  = threadIdx.x;
    int* Q = g_offs + sb * (CELLS + 1);
    const int base = 1 + t * SEG;

    int s = 0;
#pragma unroll
    for (int k = 0; k < SEG; ++k) s += Q[base + k];

    __shared__ int ws[32];
    int lane = t & 31, wid = t >> 5;
    int v = s;
#pragma unroll
    for (int d = 1; d < 32; d <<= 1) {
        int n = __shfl_up_sync(0xFFFFFFFFu, v, d);
        if (lane >= d) v += n;
    }
    if (lane == 31) ws[wid] = v;
    __syncthreads();
    if (wid == 0) {
        int w = ws[lane];
#pragma unroll
        for (int d = 1; d < 32; d <<= 1) {
            int n = __shfl_up_sync(0xFFFFFFFFu, w, d);
            if (lane >= d) w += n;
        }
        ws[lane] = w;
    }
    __syncthreads();
    int run = v - s + (wid ? ws[wid - 1] : 0);

#pragma unroll
    for (int k = 0; k < SEG; ++k) {
        int tmp = Q[base + k];
        Q[base + k] = run;
        run += tmp;
    }
}

// 4. scatter; atomicAdd on offs[c+1] leaves inclusive end of cell c
__global__ __launch_bounds__(256)
void k_scatter(const float* __restrict__ gts, const float* __restrict__ preds) {
    int idx = blockIdx.x * 256 + threadIdx.x;
    int sb  = idx >> 13;
    int i   = idx & (NPTS - 1);
    int side = sb >> 3, b = sb & 7;
    const float* p = (side == 0 ? gts : preds) + ((size_t)b * NPTS + i) * 3;
    float x = p[0], y = p[1], z = p[2];
    int cx, cy, cz;
    cell_of(x, y, z, cx, cy, cz);
    int c   = (cz * G + cy) * G + cx;
    int pos = atomicAdd(&g_offs[sb * (CELLS + 1) + c + 1], 1);
    g_sorted[sb * NPTS + pos] = make_float4(x, y, z, x * x + y * y + z * z);
    g_sidx  [sb * NPTS + pos] = i;
}

// 5. exact NN query with center-cell-first lower-bound pruning
__global__ __launch_bounds__(256)
void k_query() {
    __shared__ unsigned sbits[NROWS];

    int idx  = blockIdx.x * 256 + threadIdx.x;
    int qsb  = idx >> 13;
    int slot = idx & (NPTS - 1);
    int gsb  = qsb ^ 8;

#pragma unroll
    for (int k = 0; k < NROWS / 256; ++k)
        sbits[threadIdx.x + k * 256] = g_bits[gsb * NROWS + threadIdx.x + k * 256];
    __syncthreads();

    float4 q = g_sorted[qsb * NPTS + slot];      // q.w = |q|^2
    const float mqx = -2.0f * q.x;
    const float mqy = -2.0f * q.y;
    const float mqz = -2.0f * q.z;
    int cx, cy, cz;
    cell_of(q.x, q.y, q.z, cx, cy, cz);

    // fractional position inside the home cell -> distances to cell walls
    float fx = (q.x + RANGE) * INVH - (float)cx;
    float fy = (q.y + RANGE) * INVH - (float)cy;
    float fz = (q.z + RANGE) * INVH - (float)cz;
    float dxm = fx * HCELL, dxp = (1.0f - fx) * HCELL;
    float dym = fy * HCELL, dyp = (1.0f - fy) * HCELL;
    float dzm = fz * HCELL, dzp = (1.0f - fz) * HCELL;

    const int*    offs = g_offs + gsb * (CELLS + 1);
    const float4* pts  = g_sorted + (size_t)gsb * NPTS;

    float best = FINF;   // min over t = b2 - 2 q.b ; d2 = q.w + best

#define SCAN_RUN(S, E)                                                       \
    {                                                                        \
        int s_ = (S), e_ = (E);                                              \
        for (; s_ + 4 <= e_; s_ += 4) {                                      \
            float4 p0 = pts[s_ + 0];                                         \
            float4 p1 = pts[s_ + 1];                                         \
            float4 p2 = pts[s_ + 2];                                         \
            float4 p3 = pts[s_ + 3];                                         \
            float t0 = fmaf(mqz, p0.z, fmaf(mqy, p0.y, fmaf(mqx, p0.x, p0.w))); \
            float t1 = fmaf(mqz, p1.z, fmaf(mqy, p1.y, fmaf(mqx, p1.x, p1.w))); \
            float t2 = fmaf(mqz, p2.z, fmaf(mqy, p2.y, fmaf(mqx, p2.x, p2.w))); \
            float t3 = fmaf(mqz, p3.z, fmaf(mqy, p3.y, fmaf(mqx, p3.x, p3.w))); \
            best = fminf(best, fminf(fminf(t0, t1), fminf(t2, t3)));         \
        }                                                                    \
        for (; s_ < e_; ++s_) {                                              \
            float4 p = pts[s_];                                              \
            best = fminf(best,                                               \
                fmaf(mqz, p.z, fmaf(mqy, p.y, fmaf(mqx, p.x, p.w))));        \
        }                                                                    \
    }

    // ---- Phase 1a: home cell first (tightest bd2 earliest), then x-neighbor
    // cells of the center row only if their wall distance can beat best.
    {
        int rowi = cz * G + cy;
        int rowb = rowi * G;
        unsigned mc = sbits[rowi];
        if (mc & (1u << cx))
            SCAN_RUN(offs[rowb + cx], offs[rowb + cx + 1]);
        float bd2 = q.w + best;
        if (cx - 1 >= 0 && (mc & (1u << (cx - 1))) && dxm * dxm < bd2)
            SCAN_RUN(offs[rowb + cx - 1], offs[rowb + cx]);
        bd2 = q.w + best;
        if (cx + 1 < G && (mc & (1u << (cx + 1))) && dxp * dxp < bd2)
            SCAN_RUN(offs[rowb + cx + 1], offs[rowb + cx + 2]);
    }

    // ---- Phase 1b: 8 remaining rows, row-level + per-cell x pruning.
    // Faces first (tighter best earlier), then corners.
    {
        const signed char RY[8] = {-1,  1,  0,  0, -1, -1,  1,  1};
        const signed char RZ[8] = { 0,  0, -1,  1, -1,  1, -1,  1};
#pragma unroll
        for (int k = 0; k < 8; ++k) {
            int dy = RY[k], dz = RZ[k];
            int y = cy + dy, z = cz + dz;
            if ((unsigned)y >= G || (unsigned)z >= G) continue;
            float lby = (dy > 0) ? dyp : ((dy < 0) ? dym : 0.0f);
            float lbz = (dz > 0) ? dzp : ((dz < 0) ? dzm : 0.0f);
            float lb2 = lby * lby + lbz * lbz;
            float bd2 = q.w + best;
            if (lb2 >= bd2) continue;

            unsigned xm = 1u << cx;
            if (cx - 1 >= 0 && lb2 + dxm * dxm < bd2) xm |= 1u << (cx - 1);
            if (cx + 1 <  G && lb2 + dxp * dxp < bd2) xm |= 1u << (cx + 1);
            unsigned m = sbits[z * G + y] & xm;
            if (!m) continue;
            int x0 = __ffs(m) - 1;
            int x1 = 31 - __clz(m);
            int rowb = (z * G + y) * G;
            SCAN_RUN(offs[rowb + x0], offs[rowb + x1 + 1]);
        }
    }

    // ---- Phase 2: rare tail, ring expansion (exact bound: after finishing
    // ring r, every unscanned point is >= r*HCELL away).
    if (q.w + best > HCELL * HCELL) {
        for (int r = 2; r <= G; ++r) {
            int zlo = max(cz - r, 0), zhi = min(cz + r, G - 1);
            for (int z = zlo; z <= zhi; ++z) {
                int adz = abs(z - cz);
                int ylo = max(cy - r, 0), yhi = min(cy + r, G - 1);
                for (int y = ylo; y <= yhi; ++y) {
                    int ady = abs(y - cy);
                    int row = z * G + y;
                    unsigned m;
                    if (adz == r || ady == r) {
                        m = sbits[row] &
                            range_mask(max(cx - r, 0), min(cx + r, G - 1));
                    } else {
                        unsigned em = 0;
                        if (cx - r >= 0) em |= 1u << (cx - r);
                        if (cx + r < G)  em |= 1u << (cx + r);
                        m = sbits[row] & em;
                    }
                    while (m) {
                        int x = __ffs(m) - 1;
                        m &= m - 1;
                        int c = row * G + x;
                        SCAN_RUN(offs[c], offs[c + 1]);
                    }
                }
            }
            float rb = (float)r * HCELL;
            if (q.w + best <= rb * rb) break;
        }
    }
#undef SCAN_RUN

    float v = fmaxf(q.w + best, 0.0f);   // d2 clamped (matches reference)
    g_minbuf[qsb * NPTS + g_sidx[qsb * NPTS + slot]] = v;
}

// 6. deterministic block-tree partial sums (fixed index order)
__global__ __launch_bounds__(256)
void k_reduce() {
    __shared__ float red[256];
    int i = blockIdx.x * 256 + threadIdx.x;
    red[threadIdx.x] = g_minbuf[i];
    __syncthreads();
#pragma unroll
    for (int s = 128; s > 0; s >>= 1) {
        if (threadIdx.x < s) red[threadIdx.x] += red[threadIdx.x + s];
        __syncthreads();
    }
    if (threadIdx.x == 0) g_blocksums[blockIdx.x] = red[0];
}

// 7. final: sum 512 partials; shared denominator BATCH*NPTS
__global__ void k_final(float* __restrict__ out) {
    __shared__ float red[512];
    red[threadIdx.x] = g_blocksums[threadIdx.x];
    __syncthreads();
#pragma unroll
    for (int s = 256; s > 0; s >>= 1) {
        if (threadIdx.x < s) red[threadIdx.x] += red[threadIdx.x + s];
        __syncthreads();
    }
    if (threadIdx.x == 0)
        out[0] = red[0] / (float)(BATCH * NPTS);
}

extern "C" void kernel_launch(void* const* d_in, const int* in_sizes, int n_in,
                              void* d_out, int out_size) {
    const float* gts   = (const float*)d_in[0];
    const float* preds = (const float*)d_in[1];
    (void)in_sizes; (void)n_in; (void)out_size;

    k_zero<<<512, 256>>>();
    k_count<<<NTOT / 256, 256>>>(gts, preds);
    k_scan<<<NSB, 1024>>>();
    k_scatter<<<NTOT / 256, 256>>>(gts, preds);
    k_query<<<NTOT / 256, 256>>>();
    k_reduce<<<NTOT / 256, 256>>>();
    k_final<<<1, 512>>>((float*)d_out);
}